// round 5
// baseline (speedup 1.0000x reference)
#include <cuda_runtime.h>
#include <math.h>
#include <stdint.h>

#define D_MODEL 1024
#define S_LEN   2048
#define BATCH   2
#define HEADS   16
#define DEPTH   64
#define ROWS    (BATCH * S_LEN)     // 4096
#define BH      (BATCH * HEADS)     // 32

#define OUT_ELEMS  ((size_t)ROWS * D_MODEL)
#define ATTN_ELEMS ((size_t)BH * S_LEN * S_LEN)

__device__ float g_q[ROWS * D_MODEL];
__device__ float g_k[ROWS * D_MODEL];
__device__ float g_v[ROWS * D_MODEL];
__device__ float g_ctx[ROWS * D_MODEL];
__device__ float g_attn_scratch[ATTN_ELEMS];

// ---------------------------------------------------------------------------
#define CPA(dst, src) asm volatile("cp.async.cg.shared.global [%0], [%1], 16;" :: "r"(dst), "l"(src))
#define CPC()         asm volatile("cp.async.commit_group;")
#define CPW(n)        asm volatile("cp.async.wait_group %0;" :: "n"(n))

__device__ __forceinline__ uint32_t f2tf32(float x) {
    uint32_t r;
    asm("cvt.rna.tf32.f32 %0, %1;" : "=r"(r) : "f"(x));
    return r;
}

__device__ __forceinline__ void mma8(float* c, const uint32_t* a, const uint32_t* b) {
    asm volatile(
        "mma.sync.aligned.m16n8k8.row.col.f32.tf32.tf32.f32 "
        "{%0,%1,%2,%3}, {%4,%5,%6,%7}, {%8,%9}, {%0,%1,%2,%3};"
        : "+f"(c[0]), "+f"(c[1]), "+f"(c[2]), "+f"(c[3])
        : "r"(a[0]), "r"(a[1]), "r"(a[2]), "r"(a[3]), "r"(b[0]), "r"(b[1]));
}

__device__ __forceinline__ uint32_t sptr(const void* p) {
    return (uint32_t)__cvta_generic_to_shared(p);
}

// ---------------------------------------------------------------------------
// NN GEMM + bias, up to 3 weight segments (QKV fused). BM=128 BN=128 BK=32.
// ---------------------------------------------------------------------------
__global__ void __launch_bounds__(256, 2) gemm_x3(
    const float* __restrict__ A,
    const float* __restrict__ B0, const float* __restrict__ B1, const float* __restrict__ B2,
    const float* __restrict__ bi0, const float* __restrict__ bi1, const float* __restrict__ bi2,
    float* __restrict__ C0, float* __restrict__ C1, float* __restrict__ C2) {
    extern __shared__ float sm[];
    float* AsB = sm;            // 2 * 4608
    float* BsB = sm + 9216;     // 2 * 4352

    const int K = D_MODEL, N = D_MODEL;
    const int sel = blockIdx.x >> 3;
    const float* B    = sel == 0 ? B0  : (sel == 1 ? B1  : B2);
    const float* bias = sel == 0 ? bi0 : (sel == 1 ? bi1 : bi2);
    float* C          = sel == 0 ? C0  : (sel == 1 ? C1  : C2);
    const int n0 = (blockIdx.x & 7) * 128;
    const int m0 = blockIdx.y * 128;

    const int tid = threadIdx.x, lane = tid & 31, warp = tid >> 5;
    const int wm = warp >> 2, wn = warp & 3;
    const int g = lane >> 2, tg = lane & 3;
    const int arow = tid >> 3, acol = (tid & 7) * 4;
    const int bk = tid >> 5, bcol = (tid & 31) * 4;

    float acc[4][4][4] = {};

#define PREFETCH_G(kt, buf) {                                                    \
        float* As_ = AsB + (buf) * 4608;                                         \
        float* Bs_ = BsB + (buf) * 4352;                                         \
        _Pragma("unroll")                                                        \
        for (int i = 0; i < 4; i++)                                              \
            CPA(sptr(&As_[(arow + i * 32) * 36 + acol]),                         \
                A + (size_t)(m0 + arow + i * 32) * K + (kt) + acol);             \
        _Pragma("unroll")                                                        \
        for (int i = 0; i < 4; i++)                                              \
            CPA(sptr(&Bs_[(bk + i * 8) * 136 + bcol]),                           \
                B + (size_t)((kt) + bk + i * 8) * N + n0 + bcol);                \
    }

    PREFETCH_G(0, 0); CPC();

    const int NT = K / 32;
    for (int t = 0; t < NT; t++) {
        CPW(0);
        __syncthreads();
        if (t + 1 < NT) { PREFETCH_G((t + 1) * 32, (t + 1) & 1); CPC(); }

        const float* As = AsB + (t & 1) * 4608;
        const float* Bs = BsB + (t & 1) * 4352;
        #pragma unroll
        for (int kk = 0; kk < 32; kk += 8) {
            uint32_t a[4][4], b[4][2];
            #pragma unroll
            for (int mi = 0; mi < 4; mi++) {
                int r = wm * 64 + mi * 16 + g;
                a[mi][0] = f2tf32(As[r * 36 + kk + tg]);
                a[mi][1] = f2tf32(As[(r + 8) * 36 + kk + tg]);
                a[mi][2] = f2tf32(As[r * 36 + kk + tg + 4]);
                a[mi][3] = f2tf32(As[(r + 8) * 36 + kk + tg + 4]);
            }
            #pragma unroll
            for (int ni = 0; ni < 4; ni++) {
                int c = wn * 32 + ni * 8 + g;
                b[ni][0] = f2tf32(Bs[(kk + tg) * 136 + c]);
                b[ni][1] = f2tf32(Bs[(kk + tg + 4) * 136 + c]);
            }
            #pragma unroll
            for (int mi = 0; mi < 4; mi++)
                #pragma unroll
                for (int ni = 0; ni < 4; ni++)
                    mma8(acc[mi][ni], a[mi], b[ni]);
        }
        __syncthreads();
    }
#undef PREFETCH_G

    #pragma unroll
    for (int mi = 0; mi < 4; mi++) {
        int r = m0 + wm * 64 + mi * 16 + g;
        #pragma unroll
        for (int ni = 0; ni < 4; ni++) {
            int c = n0 + wn * 32 + ni * 8 + 2 * tg;
            float b0 = bias[c], b1 = bias[c + 1];
            *(float2*)(C + (size_t)r * N + c) =
                make_float2(acc[mi][ni][0] + b0, acc[mi][ni][1] + b1);
            *(float2*)(C + (size_t)(r + 8) * N + c) =
                make_float2(acc[mi][ni][2] + b0, acc[mi][ni][3] + b1);
        }
    }
}

// ---------------------------------------------------------------------------
// Fused attention: per CTA = one (b,h) and a 128-row q strip.
// Pass 1: S = Q@K^T (16 k-tiles of 128), E = exp(S/8) -> write unnormalized E
//         to attn, accumulate row sums in smem (CTA owns full rows).
// Pass 2: stream E back (L2-resident), write normalized attn, and accumulate
//         ctx = (E*inv_rowsum) @ V with tf32 mma. Exact, non-atomic ctx.
// Smem: Qs[128][68] | KE region (pass1: Ks 2x[128][68]; pass2: Es 2x[128][68])
//       | Vs 2x[64][72] | rs[128]  = 35456 floats = 141824 B.
// ---------------------------------------------------------------------------
__global__ void __launch_bounds__(256, 1) fused_attn(
    const float* __restrict__ q, const float* __restrict__ kmat,
    const float* __restrict__ v, float* __restrict__ attn,
    float* __restrict__ ctx) {
    extern __shared__ float sm[];
    float* Qs = sm;                       // 8704
    float* KE = sm + 8704;                // 17408 (2 x 8704)
    float* Vsb = sm + 8704 + 17408;       // 9216 (2 x 4608)
    float* rs = sm + 8704 + 17408 + 9216; // 128

    const int bh = blockIdx.y;
    const int bb = bh >> 4, h = bh & 15;
    const float* Qh = q    + (size_t)bb * S_LEN * D_MODEL + h * DEPTH;
    const float* Kh = kmat + (size_t)bb * S_LEN * D_MODEL + h * DEPTH;
    const float* Vh = v    + (size_t)bb * S_LEN * D_MODEL + h * DEPTH;
    const int q0 = blockIdx.x * 128;
    float* Ap = attn + (size_t)bh * S_LEN * S_LEN + (size_t)q0 * S_LEN;
    float* Cp = ctx + (size_t)bb * S_LEN * D_MODEL + (size_t)q0 * D_MODEL + h * DEPTH;

    const int tid = threadIdx.x, lane = tid & 31, warp = tid >> 5;
    const int wm = warp >> 2, wn = warp & 3;
    const int g = lane >> 2, tg = lane & 3;

    if (tid < 128) rs[tid] = 0.f;

    // Prefetch Q strip (128x64) + K tile 0 (128x64) in one group
    #pragma unroll
    for (int i = 0; i < 8; i++) {
        int j = i * 256 + tid;
        int r = j >> 4, c = (j & 15) * 4;
        CPA(sptr(&Qs[r * 68 + c]), Qh + (size_t)(q0 + r) * D_MODEL + c);
    }
    #pragma unroll
    for (int i = 0; i < 8; i++) {
        int j = i * 256 + tid;
        int r = j >> 4, c = (j & 15) * 4;
        CPA(sptr(&KE[r * 68 + c]), Kh + (size_t)r * D_MODEL + c);
    }
    CPC();

    // ---------------- Pass 1 ----------------
    for (int t = 0; t < 16; t++) {
        CPW(0);
        __syncthreads();
        if (t + 1 < 16) {
            float* Kn = KE + ((t + 1) & 1) * 8704;
            #pragma unroll
            for (int i = 0; i < 8; i++) {
                int j = i * 256 + tid;
                int r = j >> 4, c = (j & 15) * 4;
                CPA(sptr(&Kn[r * 68 + c]), Kh + (size_t)((t + 1) * 128 + r) * D_MODEL + c);
            }
            CPC();
        }
        const float* Ks = KE + (t & 1) * 8704;

        float acc[4][4][4] = {};
        #pragma unroll
        for (int kk = 0; kk < 64; kk += 8) {
            uint32_t a[4][4], b[4][2];
            #pragma unroll
            for (int mi = 0; mi < 4; mi++) {
                int r = wm * 64 + mi * 16 + g;
                a[mi][0] = f2tf32(Qs[r * 68 + kk + tg]);
                a[mi][1] = f2tf32(Qs[(r + 8) * 68 + kk + tg]);
                a[mi][2] = f2tf32(Qs[r * 68 + kk + tg + 4]);
                a[mi][3] = f2tf32(Qs[(r + 8) * 68 + kk + tg + 4]);
            }
            #pragma unroll
            for (int ni = 0; ni < 4; ni++) {
                int c = wn * 32 + ni * 8 + g;
                b[ni][0] = f2tf32(Ks[c * 68 + kk + tg]);
                b[ni][1] = f2tf32(Ks[c * 68 + kk + tg + 4]);
            }
            #pragma unroll
            for (int mi = 0; mi < 4; mi++)
                #pragma unroll
                for (int ni = 0; ni < 4; ni++)
                    mma8(acc[mi][ni], a[mi], b[ni]);
        }

        // exp, row-sum partials, write unnormalized E
        #pragma unroll
        for (int mi = 0; mi < 4; mi++) {
            float sa = 0.f, sb = 0.f;
            #pragma unroll
            for (int ni = 0; ni < 4; ni++) {
                acc[mi][ni][0] = __expf(acc[mi][ni][0] * 0.125f);
                acc[mi][ni][1] = __expf(acc[mi][ni][1] * 0.125f);
                acc[mi][ni][2] = __expf(acc[mi][ni][2] * 0.125f);
                acc[mi][ni][3] = __expf(acc[mi][ni][3] * 0.125f);
                sa += acc[mi][ni][0] + acc[mi][ni][1];
                sb += acc[mi][ni][2] + acc[mi][ni][3];
            }
            sa += __shfl_xor_sync(0xffffffffu, sa, 1);
            sa += __shfl_xor_sync(0xffffffffu, sa, 2);
            sb += __shfl_xor_sync(0xffffffffu, sb, 1);
            sb += __shfl_xor_sync(0xffffffffu, sb, 2);
            if (tg == 0) {
                atomicAdd(&rs[wm * 64 + mi * 16 + g], sa);
                atomicAdd(&rs[wm * 64 + mi * 16 + g + 8], sb);
            }
            int r = wm * 64 + mi * 16 + g;
            #pragma unroll
            for (int ni = 0; ni < 4; ni++) {
                int c = t * 128 + wn * 32 + ni * 8 + 2 * tg;
                *(float2*)(Ap + (size_t)r * S_LEN + c) =
                    make_float2(acc[mi][ni][0], acc[mi][ni][1]);
                *(float2*)(Ap + (size_t)(r + 8) * S_LEN + c) =
                    make_float2(acc[mi][ni][2], acc[mi][ni][3]);
            }
        }
        __syncthreads();
    }

    // invert row sums
    if (tid < 128) rs[tid] = 1.0f / rs[tid];
    __syncthreads();

    // ---------------- Pass 2 ----------------
    // Prefetch E tile 0 (128x64 from attn strip) + V tile 0 (64x64)
    #pragma unroll
    for (int i = 0; i < 8; i++) {
        int j = i * 256 + tid;
        int r = j >> 4, c = (j & 15) * 4;
        CPA(sptr(&KE[r * 68 + c]), Ap + (size_t)r * S_LEN + c);
    }
    #pragma unroll
    for (int i = 0; i < 4; i++) {
        int j = i * 256 + tid;
        int r = j >> 4, c = (j & 15) * 4;
        CPA(sptr(&Vsb[r * 72 + c]), Vh + (size_t)r * D_MODEL + c);
    }
    CPC();

    const float invA = rs[16 * warp + g];
    const float invB = rs[16 * warp + g + 8];

    float acc2[8][4] = {};

    for (int t = 0; t < 32; t++) {
        CPW(0);
        __syncthreads();
        if (t + 1 < 32) {
            float* En = KE + ((t + 1) & 1) * 8704;
            float* Vn = Vsb + ((t + 1) & 1) * 4608;
            #pragma unroll
            for (int i = 0; i < 8; i++) {
                int j = i * 256 + tid;
                int r = j >> 4, c = (j & 15) * 4;
                CPA(sptr(&En[r * 68 + c]), Ap + (size_t)r * S_LEN + (t + 1) * 64 + c);
            }
            #pragma unroll
            for (int i = 0; i < 4; i++) {
                int j = i * 256 + tid;
                int r = j >> 4, c = (j & 15) * 4;
                CPA(sptr(&Vn[r * 72 + c]), Vh + (size_t)((t + 1) * 64 + r) * D_MODEL + c);
            }
            CPC();
        }
        const float* Es = KE + (t & 1) * 8704;
        const float* Vs = Vsb + (t & 1) * 4608;

        // write normalized attn for this tile
        #pragma unroll
        for (int i = 0; i < 8; i++) {
            int j = i * 256 + tid;
            int r = j >> 4, c = (j & 15) * 4;
            float inv = rs[r];
            float4 ev = *(const float4*)(Es + r * 68 + c);
            ev.x *= inv; ev.y *= inv; ev.z *= inv; ev.w *= inv;
            *(float4*)(Ap + (size_t)r * S_LEN + t * 64 + c) = ev;
        }

        // ctx mma: rows 16*warp..16*warp+15, cols 0..63
        #pragma unroll
        for (int kk = 0; kk < 64; kk += 8) {
            uint32_t a[4], b[8][2];
            {
                int r = 16 * warp + g;
                a[0] = f2tf32(Es[r * 68 + kk + tg] * invA);
                a[1] = f2tf32(Es[(r + 8) * 68 + kk + tg] * invB);
                a[2] = f2tf32(Es[r * 68 + kk + tg + 4] * invA);
                a[3] = f2tf32(Es[(r + 8) * 68 + kk + tg + 4] * invB);
            }
            #pragma unroll
            for (int ni = 0; ni < 8; ni++) {
                int c = ni * 8 + g;
                b[ni][0] = f2tf32(Vs[(kk + tg) * 72 + c]);
                b[ni][1] = f2tf32(Vs[(kk + tg + 4) * 72 + c]);
            }
            #pragma unroll
            for (int ni = 0; ni < 8; ni++)
                mma8(acc2[ni], a, b[ni]);
        }
        __syncthreads();
    }

    // write ctx
    #pragma unroll
    for (int ni = 0; ni < 8; ni++) {
        int c = ni * 8 + 2 * tg;
        int r = 16 * warp + g;
        *(float2*)(Cp + (size_t)r * D_MODEL + c) = make_float2(acc2[ni][0], acc2[ni][1]);
        *(float2*)(Cp + (size_t)(r + 8) * D_MODEL + c) = make_float2(acc2[ni][2], acc2[ni][3]);
    }
}

// ---------------------------------------------------------------------------
extern "C" void kernel_launch(void* const* d_in, const int* in_sizes, int n_in,
                              void* d_out, int out_size) {
    const float* x  = (const float*)d_in[0];
    const float* wq = (const float*)d_in[1];
    const float* bq = (const float*)d_in[2];
    const float* wk = (const float*)d_in[3];
    const float* bk = (const float*)d_in[4];
    const float* wv = (const float*)d_in[5];
    const float* bv = (const float*)d_in[6];
    const float* wo = (const float*)d_in[7];
    const float* bo = (const float*)d_in[8];

    float* out = (float*)d_out;

    float *qp, *kp, *vp, *cp, *attn_scratch;
    cudaGetSymbolAddress((void**)&qp, g_q);
    cudaGetSymbolAddress((void**)&kp, g_k);
    cudaGetSymbolAddress((void**)&vp, g_v);
    cudaGetSymbolAddress((void**)&cp, g_ctx);
    cudaGetSymbolAddress((void**)&attn_scratch, g_attn_scratch);

    float* attn;
    bool write_out = true;
    if ((size_t)out_size >= OUT_ELEMS + ATTN_ELEMS) {
        attn = out + OUT_ELEMS;
    } else if ((size_t)out_size == ATTN_ELEMS) {
        attn = out;
        write_out = false;
    } else {
        attn = attn_scratch;
    }

    const int GEMM_SMEM  = (9216 + 8704) * 4;            // 71680
    const int FUSED_SMEM = (8704 + 17408 + 9216 + 128) * 4;  // 141824
    cudaFuncSetAttribute(gemm_x3,    cudaFuncAttributeMaxDynamicSharedMemorySize, GEMM_SMEM);
    cudaFuncSetAttribute(fused_attn, cudaFuncAttributeMaxDynamicSharedMemorySize, FUSED_SMEM);

    // Fused QKV projections
    gemm_x3<<<dim3(24, ROWS / 128), 256, GEMM_SMEM>>>(
        x, wq, wk, wv, bq, bk, bv, qp, kp, vp);

    // Fused attention (logits + softmax + context in one launch)
    fused_attn<<<dim3(S_LEN / 128, BH), 256, FUSED_SMEM>>>(qp, kp, vp, attn, cp);

    // Output projection
    if (write_out) {
        gemm_x3<<<dim3(8, ROWS / 128), 256, GEMM_SMEM>>>(
            cp, wo, wo, wo, bo, bo, bo, out, out, out);
    }
}